// round 1
// baseline (speedup 1.0000x reference)
#include <cuda_runtime.h>
#include <cuda_bf16.h>
#include <math.h>

// ---------------------------------------------------------------------------
// AuxLossFreeGate (DeepSeek-V3 style gate)
//   x:      (T, 2048) f32
//   weight: (256, 2048) f32
//   bias:   (256,) f32
// Output buffer (float32): [ weights (T,8) ; indices-as-float (T,8) ]
//
// Stage 1: scores = sigmoid(x @ W^T)   -> g_scores scratch (device global)
// Stage 2: per-token gating (group top2-sum, top4 groups, top8 experts)
// ---------------------------------------------------------------------------

#define N_EXPERTS   256
#define DIM_K       2048
#define N_GROUPS    8
#define EPG         32          // experts per group
#define TOPK        8
#define TOPK_GROUPS 4
#define ROUTE_SCALE 2.5f
#define MAX_T       32768
#define NEG_INF_F   (-1e30f)

// 32 MB scratch for sigmoid scores (allocation-free rule: device global)
__device__ float g_scores[(size_t)MAX_T * N_EXPERTS];

// ---------------------------------------------------------------------------
// Kernel 1: fp32 SGEMM (M=T, N=256, K=2048) fused with sigmoid.
// Block tile 128x128, BK=8, 256 threads, 8x8 per-thread tile.
// ---------------------------------------------------------------------------
#define BM 128
#define BN 128
#define BK 8
#define TM 8
#define TN 8

__global__ __launch_bounds__(256, 2)
void gemm_sigmoid_kernel(const float* __restrict__ X,
                         const float* __restrict__ W,
                         int M)
{
    __shared__ float As[BK][BM];
    __shared__ float Bs[BK][BN];

    const int tid = threadIdx.x;
    const int tx  = tid & 15;       // 0..15
    const int ty  = tid >> 4;       // 0..15

    const int rowBase = blockIdx.y * BM;
    const int colBase = blockIdx.x * BN;

    // cooperative loads: each thread loads one float4 of A and one of B per BK step
    const int lrow = tid >> 1;            // 0..127
    const int lcol = (tid & 1) * 4;       // 0 or 4

    int arow = rowBase + lrow;
    if (arow >= M) arow = M - 1;          // clamp (epilogue is guarded)
    const float* xptr = X + (size_t)arow * DIM_K + lcol;
    const float* wptr = W + (size_t)(colBase + lrow) * DIM_K + lcol;

    float acc[TM][TN];
#pragma unroll
    for (int i = 0; i < TM; ++i)
#pragma unroll
        for (int j = 0; j < TN; ++j) acc[i][j] = 0.f;

    for (int k0 = 0; k0 < DIM_K; k0 += BK) {
        float4 av = *(const float4*)(xptr + k0);
        float4 bv = *(const float4*)(wptr + k0);
        As[lcol + 0][lrow] = av.x;
        As[lcol + 1][lrow] = av.y;
        As[lcol + 2][lrow] = av.z;
        As[lcol + 3][lrow] = av.w;
        Bs[lcol + 0][lrow] = bv.x;
        Bs[lcol + 1][lrow] = bv.y;
        Bs[lcol + 2][lrow] = bv.z;
        Bs[lcol + 3][lrow] = bv.w;
        __syncthreads();

#pragma unroll
        for (int k = 0; k < BK; ++k) {
            float a[TM], b[TN];
            float4 a0 = *(const float4*)&As[k][ty * TM];
            float4 a1 = *(const float4*)&As[k][ty * TM + 4];
            a[0] = a0.x; a[1] = a0.y; a[2] = a0.z; a[3] = a0.w;
            a[4] = a1.x; a[5] = a1.y; a[6] = a1.z; a[7] = a1.w;
            float4 b0 = *(const float4*)&Bs[k][tx * TN];
            float4 b1 = *(const float4*)&Bs[k][tx * TN + 4];
            b[0] = b0.x; b[1] = b0.y; b[2] = b0.z; b[3] = b0.w;
            b[4] = b1.x; b[5] = b1.y; b[6] = b1.z; b[7] = b1.w;
#pragma unroll
            for (int i = 0; i < TM; ++i)
#pragma unroll
                for (int j = 0; j < TN; ++j)
                    acc[i][j] = fmaf(a[i], b[j], acc[i][j]);
        }
        __syncthreads();
    }

    // epilogue: sigmoid -> g_scores
#pragma unroll
    for (int i = 0; i < TM; ++i) {
        const int r = rowBase + ty * TM + i;
        if (r < M) {
#pragma unroll
            for (int j = 0; j < TN; ++j) {
                const int c = colBase + tx * TN + j;
                float v = acc[i][j];
                g_scores[(size_t)r * N_EXPERTS + c] = 1.0f / (1.0f + expf(-v));
            }
        }
    }
}

// ---------------------------------------------------------------------------
// Kernel 2: gating. One warp per token; 8 warps per block.
// Lane l owns expert e = g*32 + l for each of the 8 groups g.
// ---------------------------------------------------------------------------
__global__ __launch_bounds__(256)
void gate_kernel(const float* __restrict__ bias,
                 float* __restrict__ out_w,   // (T,8)
                 float* __restrict__ out_i,   // (T,8) as float
                 int T)
{
    __shared__ float sbias[N_EXPERTS];
    if (threadIdx.x < N_EXPERTS) sbias[threadIdx.x] = bias[threadIdx.x];
    __syncthreads();

    const int warp = threadIdx.x >> 5;
    const int lane = threadIdx.x & 31;
    const int t = blockIdx.x * 8 + warp;
    if (t >= T) return;

    const float* srow = g_scores + (size_t)t * N_EXPERTS;

    float s[N_GROUPS], b[N_GROUPS];
#pragma unroll
    for (int g = 0; g < N_GROUPS; ++g) {
        s[g] = srow[g * EPG + lane];
        b[g] = s[g] + sbias[g * EPG + lane];
    }

    // group score = sum of top-2 biased scores within each group of 32 lanes
    float gsc[N_GROUPS];
#pragma unroll
    for (int g = 0; g < N_GROUPS; ++g) {
        float m1 = b[g], m2 = NEG_INF_F;
#pragma unroll
        for (int off = 16; off; off >>= 1) {
            float o1 = __shfl_xor_sync(0xffffffffu, m1, off);
            float o2 = __shfl_xor_sync(0xffffffffu, m2, off);
            float hi = fmaxf(m1, o1);
            float lo = fminf(m1, o1);
            m1 = hi;
            m2 = fmaxf(lo, fmaxf(m2, o2));
        }
        gsc[g] = m1 + m2;   // identical on all lanes
    }

    // top-4 groups (tie -> lowest group index, via strict '>' ascending scan)
    unsigned keep = 0;
#pragma unroll
    for (int it = 0; it < TOPK_GROUPS; ++it) {
        float best = NEG_INF_F; int bg = 0;
#pragma unroll
        for (int g = 0; g < N_GROUPS; ++g) {
            bool taken = (keep >> g) & 1u;
            if (!taken && gsc[g] > best) { best = gsc[g]; bg = g; }
        }
        keep |= (1u << bg);
    }

#pragma unroll
    for (int g = 0; g < N_GROUPS; ++g)
        if (!((keep >> g) & 1u)) b[g] = NEG_INF_F;

    // top-8 experts over biased scores; carry raw sigmoid score along.
    float topw[TOPK]; int topi[TOPK];
    float wsum = 0.f;
#pragma unroll
    for (int it = 0; it < TOPK; ++it) {
        float lv = NEG_INF_F; int li = 0x7fffffff; float ls = 0.f;
#pragma unroll
        for (int g = 0; g < N_GROUPS; ++g) {
            if (b[g] > lv) { lv = b[g]; li = g * EPG + lane; ls = s[g]; }
        }
        // warp argmax, tie -> lower expert index (matches jax.lax.top_k)
#pragma unroll
        for (int off = 16; off; off >>= 1) {
            float ov = __shfl_xor_sync(0xffffffffu, lv, off);
            int   oi = __shfl_xor_sync(0xffffffffu, li, off);
            float os = __shfl_xor_sync(0xffffffffu, ls, off);
            if (ov > lv || (ov == lv && oi < li)) { lv = ov; li = oi; ls = os; }
        }
        topw[it] = ls;
        topi[it] = li;
        wsum += ls;
        // knock out the winner in its owning lane
        const int wg = li >> 5, wl = li & 31;
        if (lane == wl) {
#pragma unroll
            for (int g = 0; g < N_GROUPS; ++g)
                if (g == wg) b[g] = NEG_INF_F;
        }
    }

    const float scale = ROUTE_SCALE / fmaxf(wsum, 1e-10f);
    if (lane == 0) {
#pragma unroll
        for (int j = 0; j < TOPK; ++j) {
            out_w[(size_t)t * TOPK + j] = topw[j] * scale;
            out_i[(size_t)t * TOPK + j] = (float)topi[j];
        }
    }
}

// ---------------------------------------------------------------------------
extern "C" void kernel_launch(void* const* d_in, const int* in_sizes, int n_in,
                              void* d_out, int out_size)
{
    const float* x    = (const float*)d_in[0];   // (T, 2048)
    const float* w    = (const float*)d_in[1];   // (256, 2048)
    const float* bias = (const float*)d_in[2];   // (256,)

    int T = in_sizes[0] / DIM_K;
    if (T > MAX_T) T = MAX_T;

    float* out_w = (float*)d_out;                 // first T*8 floats
    float* out_i = (float*)d_out + (size_t)T * TOPK;  // next T*8 as float

    dim3 grid1(N_EXPERTS / BN, (T + BM - 1) / BM);
    gemm_sigmoid_kernel<<<grid1, 256>>>(x, w, T);

    gate_kernel<<<(T + 7) / 8, 256>>>(bias, out_w, out_i, T);
}

// round 4
// speedup vs baseline: 1.1633x; 1.1633x over previous
#include <cuda_runtime.h>
#include <cuda_bf16.h>
#include <math.h>
#include <stdint.h>

// ---------------------------------------------------------------------------
// AuxLossFreeGate: scores = sigmoid(x @ W^T), group-limited top-k gate.
// GEMM via warp-level mma.sync bf16 with EXACT 3-way bit splitting:
//   x = x1 + x2 + x3 exactly (8+8+8 mantissa bits), same for w,
//   all 9 product planes computed -> only fp32 accumulation rounding remains.
// Two accumulator sets keep the main plane's rounding at fp32-SGEMM level.
// ---------------------------------------------------------------------------

#define N_EXPERTS   256
#define DIM_K       2048
#define N_GROUPS    8
#define EPG         32
#define TOPK        8
#define TOPK_GROUPS 4
#define ROUTE_SCALE 2.5f
#define MAX_T       32768
#define NEG_INF_F   (-1e30f)

__device__ float g_scores[(size_t)MAX_T * N_EXPERTS];

// ---------------- GEMM config ----------------
// CTA tile: 128 tokens x 128 experts. K chunk = 32. 8 warps = 4(M) x 2(N).
// SMEM holds bf16 fragments in fragment order (LDS.128 for A, LDS.64 for B).
#define KC      32
#define ABLK    144
#define APLANE  (16 * ABLK)
#define BBLK    66
#define BPLANE  (32 * BBLK)
#define SB_OFF  (3 * APLANE)
#define SMEM_U32 (SB_OFF + 3 * BPLANE)
#define SMEM_BYTES (SMEM_U32 * 4)

#define MMA_BF16(d, a, b) asm volatile( \
    "mma.sync.aligned.m16n8k16.row.col.f32.bf16.bf16.f32 " \
    "{%0,%1,%2,%3},{%4,%5,%6,%7},{%8,%9},{%0,%1,%2,%3};" \
    : "+f"((d)[0]), "+f"((d)[1]), "+f"((d)[2]), "+f"((d)[3]) \
    : "r"((a).x), "r"((a).y), "r"((a).z), "r"((a).w), "r"((b).x), "r"((b).y))

// Exact split of 4 floats into 3 bf16 planes, packed pairwise (lo=even k).
__device__ __forceinline__ void esplit4(float4 v,
                                        uint32_t p1[2], uint32_t p2[2], uint32_t p3[2])
{
    uint32_t ux = __float_as_uint(v.x) & 0xFFFF0000u;
    uint32_t uy = __float_as_uint(v.y) & 0xFFFF0000u;
    uint32_t uz = __float_as_uint(v.z) & 0xFFFF0000u;
    uint32_t uw = __float_as_uint(v.w) & 0xFFFF0000u;
    p1[0] = __byte_perm(ux, uy, 0x7632);
    p1[1] = __byte_perm(uz, uw, 0x7632);
    float rx = v.x - __uint_as_float(ux);
    float ry = v.y - __uint_as_float(uy);
    float rz = v.z - __uint_as_float(uz);
    float rw = v.w - __uint_as_float(uw);
    uint32_t vx = __float_as_uint(rx) & 0xFFFF0000u;
    uint32_t vy = __float_as_uint(ry) & 0xFFFF0000u;
    uint32_t vz = __float_as_uint(rz) & 0xFFFF0000u;
    uint32_t vw = __float_as_uint(rw) & 0xFFFF0000u;
    p2[0] = __byte_perm(vx, vy, 0x7632);
    p2[1] = __byte_perm(vz, vw, 0x7632);
    // third residual has <= 8 significant bits -> exactly bf16
    uint32_t tx = __float_as_uint(rx - __uint_as_float(vx));
    uint32_t ty = __float_as_uint(ry - __uint_as_float(vy));
    uint32_t tz = __float_as_uint(rz - __uint_as_float(vz));
    uint32_t tw = __float_as_uint(rw - __uint_as_float(vw));
    p3[0] = __byte_perm(tx, ty, 0x7632);
    p3[1] = __byte_perm(tz, tw, 0x7632);
}

__device__ __forceinline__ float sigf(float v) { return 1.0f / (1.0f + expf(-v)); }

__global__ __launch_bounds__(256)
void gemm_hmma_kernel(const float* __restrict__ X, const float* __restrict__ W)
{
    extern __shared__ uint32_t sm[];
    const int tid  = threadIdx.x;
    const int warp = tid >> 5;
    const int lane = tid & 31;

    const int mt_blk = blockIdx.x >> 1;   // 128-token tile
    const int nh     = blockIdx.x & 1;    // 128-expert half

    const float* xb = X + (size_t)mt_blk * 128 * DIM_K;
    const float* wb = W + (size_t)nh * 128 * DIM_K;

    // loader geometry: idx = tid + j*256 over 1024 float4s of the 128x32 chunk
    int goff[4], aad[4], bad[4];
#pragma unroll
    for (int j = 0; j < 4; ++j) {
        const int idx = tid + j * 256;
        const int row = idx >> 3;            // 0..127
        const int c4  = (idx & 7) * 4;       // k offset within chunk
        goff[j] = row * DIM_K + c4;
        const int ks = c4 >> 4;
        const int kb = c4 & 15;
        const int tc = (kb >> 1) & 3;
        {   // A fragment address
            const int mt = row >> 4, r = row & 15;
            const int slot = (r & 7) * 4 + tc;
            const int reg  = (r >> 3) + 2 * ((kb >> 3) & 1);
            aad[j] = (mt * 2 + ks) * ABLK + slot * 4 + (slot >> 3) * 4 + reg;
        }
        {   // B fragment address
            const int nt = row >> 3, cn = row & 7;
            const int slot = cn * 4 + tc;
            const int reg  = (kb >> 3) & 1;
            bad[j] = SB_OFF + (nt * 2 + ks) * BBLK + slot * 2 + reg;
        }
    }

    float accM[2][8][4], accS[2][8][4];
#pragma unroll
    for (int mi = 0; mi < 2; ++mi)
#pragma unroll
        for (int ni = 0; ni < 8; ++ni)
#pragma unroll
            for (int q = 0; q < 4; ++q) { accM[mi][ni][q] = 0.f; accS[mi][ni][q] = 0.f; }

    const int wmt = (warp >> 1) * 2;
    const int wnt = (warp & 1) * 8;

    float4 ra[4], rb[4];
#pragma unroll
    for (int j = 0; j < 4; ++j) {
        ra[j] = *(const float4*)(xb + goff[j]);
        rb[j] = *(const float4*)(wb + goff[j]);
    }

    for (int c = 0; c < DIM_K / KC; ++c) {
        // ---- exact-split convert + store chunk c ----
#pragma unroll
        for (int j = 0; j < 4; ++j) {
            uint32_t p1[2], p2[2], p3[2];
            esplit4(ra[j], p1, p2, p3);
            sm[aad[j]]                  = p1[0];
            sm[aad[j] + 4]              = p1[1];
            sm[aad[j] + APLANE]         = p2[0];
            sm[aad[j] + APLANE + 4]     = p2[1];
            sm[aad[j] + 2 * APLANE]     = p3[0];
            sm[aad[j] + 2 * APLANE + 4] = p3[1];
            esplit4(rb[j], p1, p2, p3);
            sm[bad[j]]                  = p1[0];
            sm[bad[j] + 2]              = p1[1];
            sm[bad[j] + BPLANE]         = p2[0];
            sm[bad[j] + BPLANE + 2]     = p2[1];
            sm[bad[j] + 2 * BPLANE]     = p3[0];
            sm[bad[j] + 2 * BPLANE + 2] = p3[1];
        }
        __syncthreads();

        // ---- prefetch next chunk ----
        if (c + 1 < DIM_K / KC) {
            const int k0 = (c + 1) * KC;
#pragma unroll
            for (int j = 0; j < 4; ++j) {
                ra[j] = *(const float4*)(xb + goff[j] + k0);
                rb[j] = *(const float4*)(wb + goff[j] + k0);
            }
        }

        // ---- compute: 9 product planes ----
#pragma unroll
        for (int ks = 0; ks < 2; ++ks) {
            uint4 af[3][2];
#pragma unroll
            for (int p = 0; p < 3; ++p)
#pragma unroll
                for (int mi = 0; mi < 2; ++mi)
                    af[p][mi] = *(const uint4*)&sm[p * APLANE +
                        ((wmt + mi) * 2 + ks) * ABLK + lane * 4 + (lane >> 3) * 4];
#pragma unroll
            for (int ni = 0; ni < 8; ++ni) {
                const int bbase = ((wnt + ni) * 2 + ks) * BBLK + lane * 2;
                uint2 b0 = *(const uint2*)&sm[SB_OFF + 0 * BPLANE + bbase];
                uint2 b1 = *(const uint2*)&sm[SB_OFF + 1 * BPLANE + bbase];
                uint2 b2 = *(const uint2*)&sm[SB_OFF + 2 * BPLANE + bbase];
                // main plane (1,1)
                MMA_BF16(accM[0][ni], af[0][0], b0);
                MMA_BF16(accM[1][ni], af[0][1], b0);
                // small planes: (1,2)(2,1)(2,2)(1,3)(3,1)(2,3)(3,2)(3,3)
                MMA_BF16(accS[0][ni], af[0][0], b1);
                MMA_BF16(accS[1][ni], af[0][1], b1);
                MMA_BF16(accS[0][ni], af[1][0], b0);
                MMA_BF16(accS[1][ni], af[1][1], b0);
                MMA_BF16(accS[0][ni], af[1][0], b1);
                MMA_BF16(accS[1][ni], af[1][1], b1);
                MMA_BF16(accS[0][ni], af[0][0], b2);
                MMA_BF16(accS[1][ni], af[0][1], b2);
                MMA_BF16(accS[0][ni], af[2][0], b0);
                MMA_BF16(accS[1][ni], af[2][1], b0);
                MMA_BF16(accS[0][ni], af[1][0], b2);
                MMA_BF16(accS[1][ni], af[1][1], b2);
                MMA_BF16(accS[0][ni], af[2][0], b1);
                MMA_BF16(accS[1][ni], af[2][1], b1);
                MMA_BF16(accS[0][ni], af[2][0], b2);
                MMA_BF16(accS[1][ni], af[2][1], b2);
            }
        }
        __syncthreads();
    }

    // ---- epilogue: (accM + accS) -> sigmoid -> g_scores ----
    const int rbase = mt_blk * 128 + (warp >> 1) * 32 + (lane >> 2);
    const int cbase = nh * 128 + (warp & 1) * 64 + (lane & 3) * 2;
#pragma unroll
    for (int mi = 0; mi < 2; ++mi) {
#pragma unroll
        for (int ni = 0; ni < 8; ++ni) {
            const int rr = rbase + mi * 16;
            const int cc = cbase + ni * 8;
            float2 v0, v1;
            v0.x = sigf(accM[mi][ni][0] + accS[mi][ni][0]);
            v0.y = sigf(accM[mi][ni][1] + accS[mi][ni][1]);
            v1.x = sigf(accM[mi][ni][2] + accS[mi][ni][2]);
            v1.y = sigf(accM[mi][ni][3] + accS[mi][ni][3]);
            *(float2*)&g_scores[(size_t)rr * N_EXPERTS + cc] = v0;
            *(float2*)&g_scores[(size_t)(rr + 8) * N_EXPERTS + cc] = v1;
        }
    }
}

// ---------------------------------------------------------------------------
// Gating kernel: one warp per token (proven correct in round 1).
// ---------------------------------------------------------------------------
__global__ __launch_bounds__(256)
void gate_kernel(const float* __restrict__ bias,
                 float* __restrict__ out_w, float* __restrict__ out_i, int T)
{
    __shared__ float sbias[N_EXPERTS];
    if (threadIdx.x < N_EXPERTS) sbias[threadIdx.x] = bias[threadIdx.x];
    __syncthreads();

    const int warp = threadIdx.x >> 5;
    const int lane = threadIdx.x & 31;
    const int t = blockIdx.x * 8 + warp;
    if (t >= T) return;

    const float* srow = g_scores + (size_t)t * N_EXPERTS;

    float s[N_GROUPS], b[N_GROUPS];
#pragma unroll
    for (int g = 0; g < N_GROUPS; ++g) {
        s[g] = srow[g * EPG + lane];
        b[g] = s[g] + sbias[g * EPG + lane];
    }

    float gsc[N_GROUPS];
#pragma unroll
    for (int g = 0; g < N_GROUPS; ++g) {
        float m1 = b[g], m2 = NEG_INF_F;
#pragma unroll
        for (int off = 16; off; off >>= 1) {
            float o1 = __shfl_xor_sync(0xffffffffu, m1, off);
            float o2 = __shfl_xor_sync(0xffffffffu, m2, off);
            float hi = fmaxf(m1, o1);
            float lo = fminf(m1, o1);
            m1 = hi;
            m2 = fmaxf(lo, fmaxf(m2, o2));
        }
        gsc[g] = m1 + m2;
    }

    unsigned keep = 0;
#pragma unroll
    for (int it = 0; it < TOPK_GROUPS; ++it) {
        float best = NEG_INF_F; int bg = 0;
#pragma unroll
        for (int g = 0; g < N_GROUPS; ++g) {
            bool taken = (keep >> g) & 1u;
            if (!taken && gsc[g] > best) { best = gsc[g]; bg = g; }
        }
        keep |= (1u << bg);
    }
#pragma unroll
    for (int g = 0; g < N_GROUPS; ++g)
        if (!((keep >> g) & 1u)) b[g] = NEG_INF_F;

    float topw[TOPK]; int topi[TOPK];
    float wsum = 0.f;
#pragma unroll
    for (int it = 0; it < TOPK; ++it) {
        float lv = NEG_INF_F; int li = 0x7fffffff; float ls = 0.f;
#pragma unroll
        for (int g = 0; g < N_GROUPS; ++g) {
            if (b[g] > lv) { lv = b[g]; li = g * EPG + lane; ls = s[g]; }
        }
#pragma unroll
        for (int off = 16; off; off >>= 1) {
            float ov = __shfl_xor_sync(0xffffffffu, lv, off);
            int   oi = __shfl_xor_sync(0xffffffffu, li, off);
            float os = __shfl_xor_sync(0xffffffffu, ls, off);
            if (ov > lv || (ov == lv && oi < li)) { lv = ov; li = oi; ls = os; }
        }
        topw[it] = ls; topi[it] = li; wsum += ls;
        const int wg = li >> 5, wl = li & 31;
        if (lane == wl) {
#pragma unroll
            for (int g = 0; g < N_GROUPS; ++g)
                if (g == wg) b[g] = NEG_INF_F;
        }
    }

    const float scale = ROUTE_SCALE / fmaxf(wsum, 1e-10f);
    if (lane == 0) {
#pragma unroll
        for (int j = 0; j < TOPK; ++j) {
            out_w[(size_t)t * TOPK + j] = topw[j] * scale;
            out_i[(size_t)t * TOPK + j] = (float)topi[j];
        }
    }
}

// ---------------------------------------------------------------------------
extern "C" void kernel_launch(void* const* d_in, const int* in_sizes, int n_in,
                              void* d_out, int out_size)
{
    const float* x    = (const float*)d_in[0];
    const float* w    = (const float*)d_in[1];
    const float* bias = (const float*)d_in[2];

    int T = in_sizes[0] / DIM_K;
    if (T > MAX_T) T = MAX_T;

    float* out_w = (float*)d_out;
    float* out_i = (float*)d_out + (size_t)T * TOPK;

    cudaFuncSetAttribute(gemm_hmma_kernel,
                         cudaFuncAttributeMaxDynamicSharedMemorySize, SMEM_BYTES);
    gemm_hmma_kernel<<<(T / 128) * 2, 256, SMEM_BYTES>>>(x, w);
    gate_kernel<<<(T + 7) / 8, 256>>>(bias, out_w, out_i, T);
}

// round 5
// speedup vs baseline: 1.3059x; 1.1226x over previous
#include <cuda_runtime.h>
#include <cuda_bf16.h>
#include <math.h>
#include <stdint.h>

// ---------------------------------------------------------------------------
// AuxLossFreeGate: scores = sigmoid(x @ W^T), group-limited top-k gate.
// GEMM via warp-level mma.sync bf16 with EXACT 3-way bit splitting
// (x = x1+x2+x3 exactly, 8+8+8 mantissa bits; same for w). 8 product planes
// (dropping x3*w3 ~ 2^-32). Term-outer MMA ordering avoids accumulator RAW
// chains; SMEM double-buffered with a single barrier per K-chunk.
// ---------------------------------------------------------------------------

#define N_EXPERTS   256
#define DIM_K       2048
#define N_GROUPS    8
#define EPG         32
#define TOPK        8
#define TOPK_GROUPS 4
#define ROUTE_SCALE 2.5f
#define MAX_T       32768
#define NEG_INF_F   (-1e30f)

__device__ float g_scores[(size_t)MAX_T * N_EXPERTS];

// ---------------- GEMM config ----------------
// CTA tile: 128 tokens x 128 experts. K chunk = 32. 8 warps = 4(M) x 2(N).
// SMEM holds bf16 fragments in fragment order (LDS.128 for A, LDS.64 for B).
#define KC      32
#define ABLK    144
#define APLANE  (16 * ABLK)
#define BBLK    66
#define BPLANE  (32 * BBLK)
#define SB_OFF  (3 * APLANE)
#define SMEM_U32 (SB_OFF + 3 * BPLANE)          // one buffer: 13248 u32
#define SMEM_BYTES (2 * SMEM_U32 * 4)           // double buffered: ~103.5 KB

#define MMA_BF16(d, a, b) asm volatile( \
    "mma.sync.aligned.m16n8k16.row.col.f32.bf16.bf16.f32 " \
    "{%0,%1,%2,%3},{%4,%5,%6,%7},{%8,%9},{%0,%1,%2,%3};" \
    : "+f"((d)[0]), "+f"((d)[1]), "+f"((d)[2]), "+f"((d)[3]) \
    : "r"((a).x), "r"((a).y), "r"((a).z), "r"((a).w), "r"((b).x), "r"((b).y))

// Exact split of 4 floats into 3 bf16 planes, packed pairwise (lo=even k).
__device__ __forceinline__ void esplit4(float4 v,
                                        uint32_t p1[2], uint32_t p2[2], uint32_t p3[2])
{
    uint32_t ux = __float_as_uint(v.x) & 0xFFFF0000u;
    uint32_t uy = __float_as_uint(v.y) & 0xFFFF0000u;
    uint32_t uz = __float_as_uint(v.z) & 0xFFFF0000u;
    uint32_t uw = __float_as_uint(v.w) & 0xFFFF0000u;
    p1[0] = __byte_perm(ux, uy, 0x7632);
    p1[1] = __byte_perm(uz, uw, 0x7632);
    float rx = v.x - __uint_as_float(ux);
    float ry = v.y - __uint_as_float(uy);
    float rz = v.z - __uint_as_float(uz);
    float rw = v.w - __uint_as_float(uw);
    uint32_t vx = __float_as_uint(rx) & 0xFFFF0000u;
    uint32_t vy = __float_as_uint(ry) & 0xFFFF0000u;
    uint32_t vz = __float_as_uint(rz) & 0xFFFF0000u;
    uint32_t vw = __float_as_uint(rw) & 0xFFFF0000u;
    p2[0] = __byte_perm(vx, vy, 0x7632);
    p2[1] = __byte_perm(vz, vw, 0x7632);
    uint32_t tx = __float_as_uint(rx - __uint_as_float(vx));
    uint32_t ty = __float_as_uint(ry - __uint_as_float(vy));
    uint32_t tz = __float_as_uint(rz - __uint_as_float(vz));
    uint32_t tw = __float_as_uint(rw - __uint_as_float(vw));
    p3[0] = __byte_perm(tx, ty, 0x7632);
    p3[1] = __byte_perm(tz, tw, 0x7632);
}

__device__ __forceinline__ float sigf(float v) { return 1.0f / (1.0f + expf(-v)); }

__global__ __launch_bounds__(256)
void gemm_hmma_kernel(const float* __restrict__ X, const float* __restrict__ W)
{
    extern __shared__ uint32_t sm[];
    const int tid  = threadIdx.x;
    const int warp = tid >> 5;
    const int lane = tid & 31;

    const int mt_blk = blockIdx.x >> 1;   // 128-token tile
    const int nh     = blockIdx.x & 1;    // 128-expert half

    const float* xb = X + (size_t)mt_blk * 128 * DIM_K;
    const float* wb = W + (size_t)nh * 128 * DIM_K;

    // loader geometry: idx = tid + j*256 over 1024 float4s of the 128x32 chunk
    int goff[4], aad[4], bad[4];
#pragma unroll
    for (int j = 0; j < 4; ++j) {
        const int idx = tid + j * 256;
        const int row = idx >> 3;            // 0..127
        const int c4  = (idx & 7) * 4;       // k offset within chunk
        goff[j] = row * DIM_K + c4;
        const int ks = c4 >> 4;
        const int kb = c4 & 15;
        const int tc = (kb >> 1) & 3;
        {   // A fragment address
            const int mt = row >> 4, r = row & 15;
            const int slot = (r & 7) * 4 + tc;
            const int reg  = (r >> 3) + 2 * ((kb >> 3) & 1);
            aad[j] = (mt * 2 + ks) * ABLK + slot * 4 + (slot >> 3) * 4 + reg;
        }
        {   // B fragment address
            const int nt = row >> 3, cn = row & 7;
            const int slot = cn * 4 + tc;
            const int reg  = (kb >> 3) & 1;
            bad[j] = SB_OFF + (nt * 2 + ks) * BBLK + slot * 2 + reg;
        }
    }

    float accM[2][8][4], accS[2][8][4];
#pragma unroll
    for (int mi = 0; mi < 2; ++mi)
#pragma unroll
        for (int ni = 0; ni < 8; ++ni)
#pragma unroll
            for (int q = 0; q < 4; ++q) { accM[mi][ni][q] = 0.f; accS[mi][ni][q] = 0.f; }

    const int wmt = (warp >> 1) * 2;
    const int wnt = (warp & 1) * 8;

    float4 ra[4], rb[4];
#pragma unroll
    for (int j = 0; j < 4; ++j) {
        ra[j] = *(const float4*)(xb + goff[j]);
        rb[j] = *(const float4*)(wb + goff[j]);
    }

    // Single barrier per chunk, double-buffered SMEM.
    // Per-warp order: ... compute(c-1) -> store(c) -> SYNC(c) -> compute(c) ...
    // store(c+1) targets the buffer last read by compute(c-1); SYNC(c) orders
    // every warp's compute(c-1) before any warp's store(c+1).  (safe)
    for (int c = 0; c < DIM_K / KC; ++c) {
        uint32_t* smb = sm + (c & 1) * SMEM_U32;

        // ---- exact-split convert + store chunk c ----
#pragma unroll
        for (int j = 0; j < 4; ++j) {
            uint32_t p1[2], p2[2], p3[2];
            esplit4(ra[j], p1, p2, p3);
            smb[aad[j]]                  = p1[0];
            smb[aad[j] + 4]              = p1[1];
            smb[aad[j] + APLANE]         = p2[0];
            smb[aad[j] + APLANE + 4]     = p2[1];
            smb[aad[j] + 2 * APLANE]     = p3[0];
            smb[aad[j] + 2 * APLANE + 4] = p3[1];
            esplit4(rb[j], p1, p2, p3);
            smb[bad[j]]                  = p1[0];
            smb[bad[j] + 2]              = p1[1];
            smb[bad[j] + BPLANE]         = p2[0];
            smb[bad[j] + BPLANE + 2]     = p2[1];
            smb[bad[j] + 2 * BPLANE]     = p3[0];
            smb[bad[j] + 2 * BPLANE + 2] = p3[1];
        }
        __syncthreads();

        // ---- prefetch next chunk (consumed by next iteration's store) ----
        if (c + 1 < DIM_K / KC) {
            const int k0 = (c + 1) * KC;
#pragma unroll
            for (int j = 0; j < 4; ++j) {
                ra[j] = *(const float4*)(xb + goff[j] + k0);
                rb[j] = *(const float4*)(wb + goff[j] + k0);
            }
        }

        // ---- compute: 8 product planes, term-outer / ni-inner ordering ----
#pragma unroll
        for (int ks = 0; ks < 2; ++ks) {
            uint4 af[3][2];
#pragma unroll
            for (int p = 0; p < 3; ++p)
#pragma unroll
                for (int mi = 0; mi < 2; ++mi)
                    af[p][mi] = *(const uint4*)&smb[p * APLANE +
                        ((wmt + mi) * 2 + ks) * ABLK + lane * 4 + (lane >> 3) * 4];

#pragma unroll
            for (int nq = 0; nq < 2; ++nq) {
                const int nb = nq * 4;
                uint2 bf[4][3];
#pragma unroll
                for (int ni4 = 0; ni4 < 4; ++ni4) {
                    const int bbase = ((wnt + nb + ni4) * 2 + ks) * BBLK + lane * 2;
#pragma unroll
                    for (int q = 0; q < 3; ++q)
                        bf[ni4][q] = *(const uint2*)&smb[SB_OFF + q * BPLANE + bbase];
                }

#define DO_TERM(DST, P_, Q_) \
                { \
                    _Pragma("unroll") \
                    for (int ni4 = 0; ni4 < 4; ++ni4) { \
                        MMA_BF16(DST[0][nb + ni4], af[P_][0], bf[ni4][Q_]); \
                        MMA_BF16(DST[1][nb + ni4], af[P_][1], bf[ni4][Q_]); \
                    } \
                }
                DO_TERM(accM, 0, 0)   // main plane
                DO_TERM(accS, 0, 1)
                DO_TERM(accS, 1, 0)
                DO_TERM(accS, 1, 1)
                DO_TERM(accS, 0, 2)
                DO_TERM(accS, 2, 0)
                DO_TERM(accS, 1, 2)
                DO_TERM(accS, 2, 1)
#undef DO_TERM
            }
        }
    }

    // ---- epilogue: (accM + accS) -> sigmoid -> g_scores ----
    const int rbase = mt_blk * 128 + (warp >> 1) * 32 + (lane >> 2);
    const int cbase = nh * 128 + (warp & 1) * 64 + (lane & 3) * 2;
#pragma unroll
    for (int mi = 0; mi < 2; ++mi) {
#pragma unroll
        for (int ni = 0; ni < 8; ++ni) {
            const int rr = rbase + mi * 16;
            const int cc = cbase + ni * 8;
            float2 v0, v1;
            v0.x = sigf(accM[mi][ni][0] + accS[mi][ni][0]);
            v0.y = sigf(accM[mi][ni][1] + accS[mi][ni][1]);
            v1.x = sigf(accM[mi][ni][2] + accS[mi][ni][2]);
            v1.y = sigf(accM[mi][ni][3] + accS[mi][ni][3]);
            *(float2*)&g_scores[(size_t)rr * N_EXPERTS + cc] = v0;
            *(float2*)&g_scores[(size_t)(rr + 8) * N_EXPERTS + cc] = v1;
        }
    }
}

// ---------------------------------------------------------------------------
// Gating kernel: one warp per token (proven correct in round 1).
// ---------------------------------------------------------------------------
__global__ __launch_bounds__(256)
void gate_kernel(const float* __restrict__ bias,
                 float* __restrict__ out_w, float* __restrict__ out_i, int T)
{
    __shared__ float sbias[N_EXPERTS];
    if (threadIdx.x < N_EXPERTS) sbias[threadIdx.x] = bias[threadIdx.x];
    __syncthreads();

    const int warp = threadIdx.x >> 5;
    const int lane = threadIdx.x & 31;
    const int t = blockIdx.x * 8 + warp;
    if (t >= T) return;

    const float* srow = g_scores + (size_t)t * N_EXPERTS;

    float s[N_GROUPS], b[N_GROUPS];
#pragma unroll
    for (int g = 0; g < N_GROUPS; ++g) {
        s[g] = srow[g * EPG + lane];
        b[g] = s[g] + sbias[g * EPG + lane];
    }

    float gsc[N_GROUPS];
#pragma unroll
    for (int g = 0; g < N_GROUPS; ++g) {
        float m1 = b[g], m2 = NEG_INF_F;
#pragma unroll
        for (int off = 16; off; off >>= 1) {
            float o1 = __shfl_xor_sync(0xffffffffu, m1, off);
            float o2 = __shfl_xor_sync(0xffffffffu, m2, off);
            float hi = fmaxf(m1, o1);
            float lo = fminf(m1, o1);
            m1 = hi;
            m2 = fmaxf(lo, fmaxf(m2, o2));
        }
        gsc[g] = m1 + m2;
    }

    unsigned keep = 0;
#pragma unroll
    for (int it = 0; it < TOPK_GROUPS; ++it) {
        float best = NEG_INF_F; int bg = 0;
#pragma unroll
        for (int g = 0; g < N_GROUPS; ++g) {
            bool taken = (keep >> g) & 1u;
            if (!taken && gsc[g] > best) { best = gsc[g]; bg = g; }
        }
        keep |= (1u << bg);
    }
#pragma unroll
    for (int g = 0; g < N_GROUPS; ++g)
        if (!((keep >> g) & 1u)) b[g] = NEG_INF_F;

    float topw[TOPK]; int topi[TOPK];
    float wsum = 0.f;
#pragma unroll
    for (int it = 0; it < TOPK; ++it) {
        float lv = NEG_INF_F; int li = 0x7fffffff; float ls = 0.f;
#pragma unroll
        for (int g = 0; g < N_GROUPS; ++g) {
            if (b[g] > lv) { lv = b[g]; li = g * EPG + lane; ls = s[g]; }
        }
#pragma unroll
        for (int off = 16; off; off >>= 1) {
            float ov = __shfl_xor_sync(0xffffffffu, lv, off);
            int   oi = __shfl_xor_sync(0xffffffffu, li, off);
            float os = __shfl_xor_sync(0xffffffffu, ls, off);
            if (ov > lv || (ov == lv && oi < li)) { lv = ov; li = oi; ls = os; }
        }
        topw[it] = ls; topi[it] = li; wsum += ls;
        const int wg = li >> 5, wl = li & 31;
        if (lane == wl) {
#pragma unroll
            for (int g = 0; g < N_GROUPS; ++g)
                if (g == wg) b[g] = NEG_INF_F;
        }
    }

    const float scale = ROUTE_SCALE / fmaxf(wsum, 1e-10f);
    if (lane == 0) {
#pragma unroll
        for (int j = 0; j < TOPK; ++j) {
            out_w[(size_t)t * TOPK + j] = topw[j] * scale;
            out_i[(size_t)t * TOPK + j] = (float)topi[j];
        }
    }
}

// ---------------------------------------------------------------------------
extern "C" void kernel_launch(void* const* d_in, const int* in_sizes, int n_in,
                              void* d_out, int out_size)
{
    const float* x    = (const float*)d_in[0];
    const float* w    = (const float*)d_in[1];
    const float* bias = (const float*)d_in[2];

    int T = in_sizes[0] / DIM_K;
    if (T > MAX_T) T = MAX_T;

    float* out_w = (float*)d_out;
    float* out_i = (float*)d_out + (size_t)T * TOPK;

    cudaFuncSetAttribute(gemm_hmma_kernel,
                         cudaFuncAttributeMaxDynamicSharedMemorySize, SMEM_BYTES);
    gemm_hmma_kernel<<<(T / 128) * 2, 256, SMEM_BYTES>>>(x, w);
    gate_kernel<<<(T + 7) / 8, 256>>>(bias, out_w, out_i, T);
}

// round 6
// speedup vs baseline: 2.5094x; 1.9216x over previous
#include <cuda_runtime.h>
#include <cuda_fp16.h>
#include <math.h>
#include <stdint.h>

// ---------------------------------------------------------------------------
// AuxLossFreeGate: scores = sigmoid(x @ W^T), group-limited top-k gate.
// GEMM via warp-level mma.sync fp16 (11-bit mantissa) with 2-way RN split:
//   x = x1 + x2*2^-12,  w = w1 + w2*2^-12   (planes RN'd to fp16, scaled 2^12)
// 3 product planes: (1,1) -> accM ; (1,2),(2,1) -> accS (scale 2^12).
// Dropped terms <= 2^-24*|x||w| (independent RN residuals, sigma ~1.4e-8 per
// logit) -- 30x below the accumulation-reorder noise proven zero-flip.
// ---------------------------------------------------------------------------

#define N_EXPERTS   256
#define DIM_K       2048
#define N_GROUPS    8
#define EPG         32
#define TOPK        8
#define TOPK_GROUPS 4
#define ROUTE_SCALE 2.5f
#define MAX_T       32768
#define NEG_INF_F   (-1e30f)

__device__ float g_scores[(size_t)MAX_T * N_EXPERTS];

// ---------------- GEMM config ----------------
// CTA tile: 128 tokens x 128 experts. K chunk = 32. 8 warps = 4(M) x 2(N).
// SMEM holds fp16 fragments in fragment order (LDS.128 for A, LDS.64 for B).
#define KC      32
#define ABLK    144
#define APLANE  (16 * ABLK)          // 2304 u32 per A plane
#define BBLK    66
#define BPLANE  (32 * BBLK)          // 2112 u32 per B plane
#define SB_OFF  (2 * APLANE)
#define SMEM_U32 (SB_OFF + 2 * BPLANE)   // one buffer: 8832 u32
#define SMEM_BYTES (2 * SMEM_U32 * 4)    // double buffered: ~69 KB

#define MMA_F16(d, a, b) asm volatile( \
    "mma.sync.aligned.m16n8k16.row.col.f32.f16.f16.f32 " \
    "{%0,%1,%2,%3},{%4,%5,%6,%7},{%8,%9},{%0,%1,%2,%3};" \
    : "+f"((d)[0]), "+f"((d)[1]), "+f"((d)[2]), "+f"((d)[3]) \
    : "r"((a).x), "r"((a).y), "r"((a).z), "r"((a).w), "r"((b).x), "r"((b).y))

// 2-way fp16 split of 4 floats, pairwise packed (even k in lo half).
// p1 = RN_fp16(v); p2 = RN_fp16((v - p1) * 2^12).
__device__ __forceinline__ void hsplit4(float4 v, uint32_t p1[2], uint32_t p2[2])
{
    __half2 a1 = __floats2half2_rn(v.x, v.y);
    __half2 b1 = __floats2half2_rn(v.z, v.w);
    p1[0] = *(uint32_t*)&a1;
    p1[1] = *(uint32_t*)&b1;
    float rx = (v.x - __half2float(__low2half(a1)))  * 4096.0f;
    float ry = (v.y - __half2float(__high2half(a1))) * 4096.0f;
    float rz = (v.z - __half2float(__low2half(b1)))  * 4096.0f;
    float rw = (v.w - __half2float(__high2half(b1))) * 4096.0f;
    __half2 a2 = __floats2half2_rn(rx, ry);
    __half2 b2 = __floats2half2_rn(rz, rw);
    p2[0] = *(uint32_t*)&a2;
    p2[1] = *(uint32_t*)&b2;
}

__device__ __forceinline__ float sigf(float v) { return 1.0f / (1.0f + expf(-v)); }

__global__ __launch_bounds__(256)
void gemm_hmma_kernel(const float* __restrict__ X, const float* __restrict__ W)
{
    extern __shared__ uint32_t sm[];
    const int tid  = threadIdx.x;
    const int warp = tid >> 5;
    const int lane = tid & 31;

    const int mt_blk = blockIdx.x >> 1;   // 128-token tile
    const int nh     = blockIdx.x & 1;    // 128-expert half

    const float* xb = X + (size_t)mt_blk * 128 * DIM_K;
    const float* wb = W + (size_t)nh * 128 * DIM_K;

    // loader geometry: idx = tid + j*256 over 1024 float4s of the 128x32 chunk
    int goff[4], aad[4], bad[4];
#pragma unroll
    for (int j = 0; j < 4; ++j) {
        const int idx = tid + j * 256;
        const int row = idx >> 3;            // 0..127
        const int c4  = (idx & 7) * 4;       // k offset within chunk
        goff[j] = row * DIM_K + c4;
        const int ks = c4 >> 4;
        const int kb = c4 & 15;
        const int tc = (kb >> 1) & 3;
        {   // A fragment address
            const int mt = row >> 4, r = row & 15;
            const int slot = (r & 7) * 4 + tc;
            const int reg  = (r >> 3) + 2 * ((kb >> 3) & 1);
            aad[j] = (mt * 2 + ks) * ABLK + slot * 4 + (slot >> 3) * 4 + reg;
        }
        {   // B fragment address
            const int nt = row >> 3, cn = row & 7;
            const int slot = cn * 4 + tc;
            const int reg  = (kb >> 3) & 1;
            bad[j] = SB_OFF + (nt * 2 + ks) * BBLK + slot * 2 + reg;
        }
    }

    float accM[2][8][4], accS[2][8][4];
#pragma unroll
    for (int mi = 0; mi < 2; ++mi)
#pragma unroll
        for (int ni = 0; ni < 8; ++ni)
#pragma unroll
            for (int q = 0; q < 4; ++q) { accM[mi][ni][q] = 0.f; accS[mi][ni][q] = 0.f; }

    const int wmt = (warp >> 1) * 2;
    const int wnt = (warp & 1) * 8;

    float4 ra[4], rb[4];
#pragma unroll
    for (int j = 0; j < 4; ++j) {
        ra[j] = *(const float4*)(xb + goff[j]);
        rb[j] = *(const float4*)(wb + goff[j]);
    }

    // Single barrier per chunk, double-buffered SMEM:
    // store(c+1) targets the buffer last read by compute(c-1); SYNC(c) orders
    // every warp's compute(c-1) before any warp's store(c+1).
    for (int c = 0; c < DIM_K / KC; ++c) {
        uint32_t* smb = sm + (c & 1) * SMEM_U32;

        // ---- fp16 2-way split convert + store chunk c ----
#pragma unroll
        for (int j = 0; j < 4; ++j) {
            uint32_t p1[2], p2[2];
            hsplit4(ra[j], p1, p2);
            smb[aad[j]]              = p1[0];
            smb[aad[j] + 4]          = p1[1];
            smb[aad[j] + APLANE]     = p2[0];
            smb[aad[j] + APLANE + 4] = p2[1];
            hsplit4(rb[j], p1, p2);
            smb[bad[j]]              = p1[0];
            smb[bad[j] + 2]          = p1[1];
            smb[bad[j] + BPLANE]     = p2[0];
            smb[bad[j] + BPLANE + 2] = p2[1];
        }
        __syncthreads();

        // ---- prefetch next chunk (consumed by next iteration's store) ----
        if (c + 1 < DIM_K / KC) {
            const int k0 = (c + 1) * KC;
#pragma unroll
            for (int j = 0; j < 4; ++j) {
                ra[j] = *(const float4*)(xb + goff[j] + k0);
                rb[j] = *(const float4*)(wb + goff[j] + k0);
            }
        }

        // ---- compute: 3 product planes, term-outer / ni-inner ordering ----
#pragma unroll
        for (int ks = 0; ks < 2; ++ks) {
            uint4 af[2][2];
#pragma unroll
            for (int p = 0; p < 2; ++p)
#pragma unroll
                for (int mi = 0; mi < 2; ++mi)
                    af[p][mi] = *(const uint4*)&smb[p * APLANE +
                        ((wmt + mi) * 2 + ks) * ABLK + lane * 4 + (lane >> 3) * 4];

#pragma unroll
            for (int nq = 0; nq < 2; ++nq) {
                const int nb = nq * 4;
                uint2 bf[4][2];
#pragma unroll
                for (int ni4 = 0; ni4 < 4; ++ni4) {
                    const int bbase = ((wnt + nb + ni4) * 2 + ks) * BBLK + lane * 2;
#pragma unroll
                    for (int q = 0; q < 2; ++q)
                        bf[ni4][q] = *(const uint2*)&smb[SB_OFF + q * BPLANE + bbase];
                }

#define DO_TERM(DST, P_, Q_) \
                { \
                    _Pragma("unroll") \
                    for (int ni4 = 0; ni4 < 4; ++ni4) { \
                        MMA_F16(DST[0][nb + ni4], af[P_][0], bf[ni4][Q_]); \
                        MMA_F16(DST[1][nb + ni4], af[P_][1], bf[ni4][Q_]); \
                    } \
                }
                DO_TERM(accM, 0, 0)   // (1,1) main plane
                DO_TERM(accS, 0, 1)   // (1,2) scale 2^12
                DO_TERM(accS, 1, 0)   // (2,1) scale 2^12
#undef DO_TERM
            }
        }
    }

    // ---- epilogue: accM + accS*2^-12 -> sigmoid -> g_scores ----
    const float INV = 1.0f / 4096.0f;
    const int rbase = mt_blk * 128 + (warp >> 1) * 32 + (lane >> 2);
    const int cbase = nh * 128 + (warp & 1) * 64 + (lane & 3) * 2;
#pragma unroll
    for (int mi = 0; mi < 2; ++mi) {
#pragma unroll
        for (int ni = 0; ni < 8; ++ni) {
            const int rr = rbase + mi * 16;
            const int cc = cbase + ni * 8;
            float2 v0, v1;
            v0.x = sigf(fmaf(accS[mi][ni][0], INV, accM[mi][ni][0]));
            v0.y = sigf(fmaf(accS[mi][ni][1], INV, accM[mi][ni][1]));
            v1.x = sigf(fmaf(accS[mi][ni][2], INV, accM[mi][ni][2]));
            v1.y = sigf(fmaf(accS[mi][ni][3], INV, accM[mi][ni][3]));
            *(float2*)&g_scores[(size_t)rr * N_EXPERTS + cc] = v0;
            *(float2*)&g_scores[(size_t)(rr + 8) * N_EXPERTS + cc] = v1;
        }
    }
}

// ---------------------------------------------------------------------------
// Gating kernel: one warp per token (proven correct since round 1).
// ---------------------------------------------------------------------------
__global__ __launch_bounds__(256)
void gate_kernel(const float* __restrict__ bias,
                 float* __restrict__ out_w, float* __restrict__ out_i, int T)
{
    __shared__ float sbias[N_EXPERTS];
    if (threadIdx.x < N_EXPERTS) sbias[threadIdx.x] = bias[threadIdx.x];
    __syncthreads();

    const int warp = threadIdx.x >> 5;
    const int lane = threadIdx.x & 31;
    const int t = blockIdx.x * 8 + warp;
    if (t >= T) return;

    const float* srow = g_scores + (size_t)t * N_EXPERTS;

    float s[N_GROUPS], b[N_GROUPS];
#pragma unroll
    for (int g = 0; g < N_GROUPS; ++g) {
        s[g] = srow[g * EPG + lane];
        b[g] = s[g] + sbias[g * EPG + lane];
    }

    float gsc[N_GROUPS];
#pragma unroll
    for (int g = 0; g < N_GROUPS; ++g) {
        float m1 = b[g], m2 = NEG_INF_F;
#pragma unroll
        for (int off = 16; off; off >>= 1) {
            float o1 = __shfl_xor_sync(0xffffffffu, m1, off);
            float o2 = __shfl_xor_sync(0xffffffffu, m2, off);
            float hi = fmaxf(m1, o1);
            float lo = fminf(m1, o1);
            m1 = hi;
            m2 = fmaxf(lo, fmaxf(m2, o2));
        }
        gsc[g] = m1 + m2;
    }

    unsigned keep = 0;
#pragma unroll
    for (int it = 0; it < TOPK_GROUPS; ++it) {
        float best = NEG_INF_F; int bg = 0;
#pragma unroll
        for (int g = 0; g < N_GROUPS; ++g) {
            bool taken = (keep >> g) & 1u;
            if (!taken && gsc[g] > best) { best = gsc[g]; bg = g; }
        }
        keep |= (1u << bg);
    }
#pragma unroll
    for (int g = 0; g < N_GROUPS; ++g)
        if (!((keep >> g) & 1u)) b[g] = NEG_INF_F;

    float topw[TOPK]; int topi[TOPK];
    float wsum = 0.f;
#pragma unroll
    for (int it = 0; it < TOPK; ++it) {
        float lv = NEG_INF_F; int li = 0x7fffffff; float ls = 0.f;
#pragma unroll
        for (int g = 0; g < N_GROUPS; ++g) {
            if (b[g] > lv) { lv = b[g]; li = g * EPG + lane; ls = s[g]; }
        }
#pragma unroll
        for (int off = 16; off; off >>= 1) {
            float ov = __shfl_xor_sync(0xffffffffu, lv, off);
            int   oi = __shfl_xor_sync(0xffffffffu, li, off);
            float os = __shfl_xor_sync(0xffffffffu, ls, off);
            if (ov > lv || (ov == lv && oi < li)) { lv = ov; li = oi; ls = os; }
        }
        topw[it] = ls; topi[it] = li; wsum += ls;
        const int wg = li >> 5, wl = li & 31;
        if (lane == wl) {
#pragma unroll
            for (int g = 0; g < N_GROUPS; ++g)
                if (g == wg) b[g] = NEG_INF_F;
        }
    }

    const float scale = ROUTE_SCALE / fmaxf(wsum, 1e-10f);
    if (lane == 0) {
#pragma unroll
        for (int j = 0; j < TOPK; ++j) {
            out_w[(size_t)t * TOPK + j] = topw[j] * scale;
            out_i[(size_t)t * TOPK + j] = (float)topi[j];
        }
    }
}

// ---------------------------------------------------------------------------
extern "C" void kernel_launch(void* const* d_in, const int* in_sizes, int n_in,
                              void* d_out, int out_size)
{
    const float* x    = (const float*)d_in[0];
    const float* w    = (const float*)d_in[1];
    const float* bias = (const float*)d_in[2];

    int T = in_sizes[0] / DIM_K;
    if (T > MAX_T) T = MAX_T;

    float* out_w = (float*)d_out;
    float* out_i = (float*)d_out + (size_t)T * TOPK;

    cudaFuncSetAttribute(gemm_hmma_kernel,
                         cudaFuncAttributeMaxDynamicSharedMemorySize, SMEM_BYTES);
    gemm_hmma_kernel<<<(T / 128) * 2, 256, SMEM_BYTES>>>(x, w);
    gate_kernel<<<(T + 7) / 8, 256>>>(bias, out_w, out_i, T);
}